// round 15
// baseline (speedup 1.0000x reference)
#include <cuda_runtime.h>

// EdgeBlock fused. B=4, L=1024, N=16, D=64, W=16, V=33.
//
// R15: R6's proven l-major gather write pattern (21 GB/s/CTA) restored, but
// at 3 CTAs/SM: stage rows 0..15 in smem (64 KB), rows 16..23 in 8 float4
// registers per thread (CTA covers a row exactly). 264 stores fully unrolled
// -> smem/register source selected at compile time; write stream identical
// to the 5764 GB/s standalone config. Both paths now fit 65.5 KB -> 444
// slots: value slot-time 26.3K us*CTA + score 10K over 444 ~= 82us,
// HBM-write-capped ~96us.
//
// Outputs (concatenated fp32 in d_out):
//   window_score (B,N,L,V)   = 2,162,688 floats
//   value_h      (B,L,V,N,D) = 138,412,032 floats (553 MB, DRAM-write bound)

#define Lc 1024
#define MASK_FILL -1e12f

__global__ void __launch_bounds__(256, 3) fused_kernel(
    const float* __restrict__ hidden,
    const int*   __restrict__ mask,
    const float* __restrict__ upon,
    const float* __restrict__ down,
    const float* __restrict__ cross,
    float*       __restrict__ out_ws,
    float4*      __restrict__ out_val)
{
    extern __shared__ float sm[];
    const int t   = threadIdx.x;
    const int bid = blockIdx.x;
    const int s   = bid >> 1;               // 0..511 within each class

    if ((bid & 1) == 0) {
        // ---- value path: 8-l tile; rows 0..15 in smem, rows 16..23 in regs ----
        float4* sh4 = (float4*)sm;           // 16 rows x 256 float4 = 64 KB
        const int b  = s >> 7;               // 0..3
        const int l0 = (s & 127) * 8;
        const float4* hidden4 = (const float4*)hidden;

#pragma unroll
        for (int r = 0; r < 16; ++r) {
            int row = (l0 + r) & (Lc - 1);
            sh4[r * 256 + t] = hidden4[((size_t)((b << 10) + row)) * 256 + t];
        }
        float4 hi[8];
#pragma unroll
        for (int r = 0; r < 8; ++r) {
            int row = (l0 + 16 + r) & (Lc - 1);
            hi[r] = __ldg(&hidden4[((size_t)((b << 10) + row)) * 256 + t]);
        }
        __syncthreads();

        // l-major contiguous write stream (proven R6 pattern)
#pragma unroll
        for (int ll = 0; ll < 8; ++ll) {
            size_t base = ((size_t)((b << 10) + l0 + ll)) * 33 * 256 + t;
#pragma unroll
            for (int v = 0; v < 33; ++v) {
                const int src = ll + ((v <= 16) ? 0 : (v - 16)); // compile-time
                float4 val = (src < 16) ? sh4[src * 256 + t] : hi[src - 16];
                __stcs(&out_val[base + (size_t)v * 256], val);
            }
        }
        return;
    }

    // ------------------------- score path: s in 0..511 -------------------------
    // (verbatim from R13/R14 — passing at 6.1e-16)
    const int tile = s & 7, n = (s >> 3) & 15, b = s >> 7;
    const int l0 = tile * 128;

    float* shC  = sm;             // [64][68]  (cross transposed: shC[h*68+d])
    float* shH  = sm + 4352;      // [160][68] (rows l0-16 .. l0+143, wrapped)
    float* su   = sm + 15232;     // [160]
    float* sd   = sm + 15392;     // [160]
    float* shup = sm + 15552;     // [64]
    float* shdn = sm + 15616;     // [64]
    int*   shm  = (int*)(sm + 15680); // [160]
    // 15,840 floats = 63,360 B < 65,536 B request

    for (int i = t; i < 4096; i += 256) {
        int d2 = i >> 6, h2 = i & 63;
        shC[h2 * 68 + d2] = cross[n * 4096 + i];
    }
    if (t < 64) { shup[t] = upon[n * 64 + t]; shdn[t] = down[n * 64 + t]; }

    {
        const float4* h4 = (const float4*)hidden;
        for (int i = t; i < 2560; i += 256) {         // 160 rows * 16 quads
            int rr = i >> 4, dq = i & 15;
            int row = (l0 - 16 + rr) & (Lc - 1);
            float4 v = h4[(((size_t)(b << 10) + row) * 16 + n) * 16 + dq];
            *(float4*)&shH[rr * 68 + dq * 4] = v;
        }
    }
    if (t < 160) shm[t] = mask[(b << 10) + ((l0 + t) & (Lc - 1))];
    __syncthreads();

    if (t < 160) {
        const float* hr = &shH[t * 68];
        float a = 0.f, c = 0.f;
#pragma unroll
        for (int dq = 0; dq < 16; ++dq) {
            float4 hv = *(const float4*)&hr[dq * 4];
            float4 up = *(const float4*)&shup[dq * 4];
            float4 dn = *(const float4*)&shdn[dq * 4];
            a += hv.x * up.x + hv.y * up.y + hv.z * up.z + hv.w * up.w;
            c += hv.x * dn.x + hv.y * dn.y + hv.z * dn.z + hv.w * dn.w;
        }
        su[t] = a; sd[t] = c;
    }
    __syncthreads();

    const int w = t >> 5, lane = t & 31;

    for (int g = 0; g < 2; ++g) {
        const int lloc0 = w * 16 + g * 8;   // 8 consecutive l's per group
        const int rb    = lloc0 + 16;       // shH row of first l

        // Phase A: qc[i][h] for 8 l's; lane owns h=lane, h=lane+32.
        float a0[8] = {0,0,0,0,0,0,0,0}, a1[8] = {0,0,0,0,0,0,0,0};
#pragma unroll
        for (int dq = 0; dq < 16; ++dq) {
            float4 c0 = *(const float4*)&shC[lane * 68 + dq * 4];
            float4 c1 = *(const float4*)&shC[(lane + 32) * 68 + dq * 4];
#pragma unroll
            for (int i = 0; i < 8; ++i) {
                float4 hd = *(const float4*)&shH[(rb + i) * 68 + dq * 4];
                a0[i] += hd.x * c0.x + hd.y * c0.y + hd.z * c0.z + hd.w * c0.w;
                a1[i] += hd.x * c1.x + hd.y * c1.y + hd.z * c1.z + hd.w * c1.w;
            }
        }

        // Phase B: 17 window products per l via shuffle reduction.
        float pk[8];
#pragma unroll
        for (int i = 0; i < 8; ++i) {
            pk[i] = 0.f;
            for (int o = 0; o < 17; ++o) {
                const float* hr = &shH[(rb + i + o) * 68];
                float p = a0[i] * hr[lane] + a1[i] * hr[lane + 32];
#pragma unroll
                for (int d2 = 16; d2 > 0; d2 >>= 1)
                    p += __shfl_xor_sync(0xffffffffu, p, d2);
                if (lane == o) pk[i] = p;
            }
        }

        // Assembly: 33 scores per l.
#pragma unroll
        for (int i = 0; i < 8; ++i) {
            const int lloc = lloc0 + i, l = l0 + lloc, rbl = rb + i;
            size_t ob = ((size_t)((b * 16 + n) * Lc + l)) * 33;

            {
                int v = lane;
                int offu = (v <= 16) ? 0 : (v - 16);
                int offd = (v <  16) ? (v - 16) : 0;
                float prod = __shfl_sync(0xffffffffu, pk[i], offu);
                float sc = prod + su[rbl + offu] + sd[rbl + offd];
                sc = (sc > 0.f) ? sc : 5.0f * sc;           // leaky_relu slope 5
                bool m = (l + offd >= 0) && (l + offu < Lc) &&
                         (shm[lloc + offu] != 0);
                __stcs(&out_ws[ob + v], m ? sc : MASK_FILL);
            }
            {
                float prod32 = __shfl_sync(0xffffffffu, pk[i], 16);
                if (lane == 0) {
                    float sc = prod32 + su[rbl + 16] + sd[rbl];
                    sc = (sc > 0.f) ? sc : 5.0f * sc;
                    bool m = (l + 16 < Lc) && (shm[lloc + 16] != 0);
                    __stcs(&out_ws[ob + 32], m ? sc : MASK_FILL);
                }
            }
        }
    }
}

extern "C" void kernel_launch(void* const* d_in, const int* in_sizes, int n_in,
                              void* d_out, int out_size) {
    const float* hidden = (const float*)d_in[0];
    const int*   mask   = (const int*)d_in[1];      // bool -> int32 on the wire
    const float* upon   = (const float*)d_in[2];
    const float* down   = (const float*)d_in[3];
    const float* cross  = (const float*)d_in[4];
    // d_in[5] (window_size) fixed at 16; compiled in.

    float*  out_ws  = (float*)d_out;
    float4* out_val = (float4*)(out_ws + (size_t)4 * 16 * Lc * 33); // 2,162,688 floats

    const int smem = 16384 * (int)sizeof(float);    // 65,536 B -> 3 CTAs/SM
    cudaFuncSetAttribute(fused_kernel, cudaFuncAttributeMaxDynamicSharedMemorySize, smem);

    // 1024 blocks, 1:1 interleave: even bid = value, odd bid = score.
    fused_kernel<<<1024, 256, smem>>>(hidden, mask, upon, down, cross,
                                      out_ws, out_val);
}